// round 1
// baseline (speedup 1.0000x reference)
#include <cuda_runtime.h>
#include <cstdint>

// ---------------------------------------------------------------------------
// RPN proposal layer for GB300.
// Phases:
//   k_zero    : clear histogram + counters
//   k_score   : decode all 4.7M boxes, validity filter, score-key + histogram
//   k_thresh  : radix-select threshold bin for top-6000 (single block)
//   k_compact : gather candidate keys (score>=threshold bin)
//   k_sort    : single-block bitonic sort of candidates (exact stable top-k)
//   k_boxes   : recompute/clip boxes for the selected 6000
//   k_mask    : 6000x6000 IoU bitmask (upper triangle, 64x64 tiles)
//   k_reduce  : group-batched greedy-NMS sequential reduce + output
// ---------------------------------------------------------------------------

#define FH 512
#define FW 768
#define HW (FH * FW)            // 393216
#define NA 12
#define NTOT (HW * NA)          // 4718592
#define NBINS (1 << 20)
#define KSHIFT 12               // histogram on top 20 bits of float
#define CAND_CAP 16384
#define PRE_N 6000
#define POST_N 300
#define NWORDS 94               // ceil(6000/64)
#define NEGF (-1e30f)

// anchor widths/heights (x2-x1+1, y2-y1+1) for the 12 base anchors;
// all base anchors share center (7.5,7.5) -> cx = x1 + 0.5*w = 8.0
__constant__ float c_aw[NA] = {92.f,184.f,368.f,736.f, 64.f,128.f,256.f,512.f, 44.f, 88.f,176.f,352.f};
__constant__ float c_ah[NA] = {48.f, 96.f,192.f,384.f, 64.f,128.f,256.f,512.f, 88.f,176.f,352.f,704.f};

__device__ __align__(16) uint32_t g_hist[NBINS];
__device__ __align__(16) uint32_t g_keys[NTOT];
__device__ unsigned long long g_cand[CAND_CAP];
__device__ int g_cand_count;
__device__ uint32_t g_thresh_bin;
__device__ int g_ntop;
__device__ float4 g_box[PRE_N];
__device__ float g_sc[PRE_N];
__device__ uint32_t g_topidx[PRE_N];
__device__ unsigned long long g_mask[PRE_N * NWORDS];

// ---------------------------------------------------------------------------
__global__ void k_zero() {
    int i = blockIdx.x * blockDim.x + threadIdx.x;
    if (i < NBINS / 4) {
        uint4 z = make_uint4(0u, 0u, 0u, 0u);
        reinterpret_cast<uint4*>(g_hist)[i] = z;
    }
    if (i == 0) g_cand_count = 0;
}

// ---------------------------------------------------------------------------
__device__ __forceinline__ float4 decode_box(int loc, int a,
                                             const float* __restrict__ bbox,
                                             float h_im, float w_im) {
    int wl = loc % FW, hl = loc / FW;
    float cx = 8.0f + 16.0f * (float)wl;
    float cy = 8.0f + 16.0f * (float)hl;
    const float* bp = bbox + (4 * a) * HW + loc;
    float dx = bp[0];
    float dy = bp[HW];
    float dw = bp[2 * HW];
    float dh = bp[3 * HW];
    float wA = c_aw[a], hA = c_ah[a];
    float pcx = dx * wA + cx;
    float pcy = dy * hA + cy;
    float pw = expf(dw) * wA;
    float ph = expf(dh) * hA;
    float4 r;
    r.x = fminf(fmaxf(pcx - 0.5f * pw, 0.0f), w_im - 1.0f);
    r.y = fminf(fmaxf(pcy - 0.5f * ph, 0.0f), h_im - 1.0f);
    r.z = fminf(fmaxf(pcx + 0.5f * pw, 0.0f), w_im - 1.0f);
    r.w = fminf(fmaxf(pcy + 0.5f * ph, 0.0f), h_im - 1.0f);
    return r;
}

__global__ void k_score(const float* __restrict__ cls,
                        const float* __restrict__ bbox,
                        const float* __restrict__ iminfo) {
    int loc = blockIdx.x * blockDim.x + threadIdx.x;
    if (loc >= HW) return;
    float h_im = iminfo[0], w_im = iminfo[1], scal = iminfo[2];
    float ms = 16.0f * scal - 1.0f;
#pragma unroll
    for (int a = 0; a < NA; a++) {
        float score = cls[(NA + a) * HW + loc];
        float4 b = decode_box(loc, a, bbox, h_im, w_im);
        bool valid = (b.z - b.x >= ms) && (b.w - b.y >= ms);
        uint32_t key = valid ? __float_as_uint(score) : 0u;
        g_keys[a * HW + loc] = key;
        if (key) atomicAdd(&g_hist[key >> KSHIFT], 1u);
    }
}

// ---------------------------------------------------------------------------
// Single block, 1024 threads. Find smallest bin T such that
// count(bin >= T) >= PRE_N (suffix scan from the top).
__global__ void k_thresh() {
    __shared__ uint32_t csum[1024];
    __shared__ uint32_t bins2[1024];
    __shared__ int s_tc;
    __shared__ long long s_above;
    int t = threadIdx.x;
    const uint4* hp = reinterpret_cast<const uint4*>(g_hist);
    uint32_t s = 0;
#pragma unroll 8
    for (int i = 0; i < 256; i++) {
        uint4 v = hp[t * 256 + i];
        s += v.x + v.y + v.z + v.w;
    }
    csum[t] = s;
    __syncthreads();
    if (t == 0) {
        long long acc = 0;
        int tc = -1;
        long long above = 0;
        for (int c = 1023; c >= 0; c--) {
            long long na = acc + (long long)csum[c];
            if (na >= PRE_N) { tc = c; above = acc; break; }
            acc = na;
        }
        if (tc < 0) { tc = 0; above = 0; }
        s_tc = tc;
        s_above = above;
    }
    __syncthreads();
    int tc = s_tc;
    bins2[t] = g_hist[tc * 1024 + t];
    __syncthreads();
    if (t == 0) {
        long long acc = s_above;
        uint32_t T = 1;
        bool found = false;
        for (int b = 1023; b >= 0; b--) {
            acc += (long long)bins2[b];
            if (acc >= PRE_N) { T = (uint32_t)(tc * 1024 + b); found = true; break; }
        }
        if (!found || T < 1) T = 1;
        g_thresh_bin = T;
    }
}

// ---------------------------------------------------------------------------
__global__ void k_compact() {
    int p = blockIdx.x * blockDim.x + threadIdx.x;
    if (p >= NTOT) return;
    uint32_t key = g_keys[p];
    uint32_t T = g_thresh_bin;
    if ((key >> KSHIFT) >= T) {
        int a = p / HW;
        int loc = p - a * HW;
        uint32_t idx = (uint32_t)(loc * NA + a);   // original flat order for tie-break
        int pos = atomicAdd(&g_cand_count, 1);
        if (pos < CAND_CAP) {
            g_cand[pos] = ((unsigned long long)key << 32) | (0xFFFFFFFFu - idx);
        }
    }
}

// ---------------------------------------------------------------------------
// Single-block bitonic sort (descending) of up to CAND_CAP 64-bit keys.
// Key = (score_bits << 32) | (~idx)  -> descending sort gives
// (score desc, idx asc), matching jax.lax.top_k stable tie-breaking.
extern __shared__ unsigned long long s_keys[];
__global__ void k_sort() {
    int n = g_cand_count;
    if (n > CAND_CAP) n = CAND_CAP;
    int np = 2;
    while (np < n) np <<= 1;
    int t = threadIdx.x;
    for (int i = t; i < np; i += blockDim.x)
        s_keys[i] = (i < n) ? g_cand[i] : 0ull;
    __syncthreads();
    for (int k = 2; k <= np; k <<= 1) {
        for (int j = k >> 1; j > 0; j >>= 1) {
            for (int i = t; i < np; i += blockDim.x) {
                int l = i ^ j;
                if (l > i) {
                    bool desc = ((i & k) == 0);
                    unsigned long long a = s_keys[i];
                    unsigned long long b = s_keys[l];
                    if ((a < b) == desc) { s_keys[i] = b; s_keys[l] = a; }
                }
            }
            __syncthreads();
        }
    }
    int ntop = (n < PRE_N) ? n : PRE_N;
    if (t == 0) g_ntop = ntop;
    for (int r = t; r < PRE_N; r += blockDim.x) {
        if (r < ntop) {
            unsigned long long kk = s_keys[r];
            g_sc[r] = __uint_as_float((uint32_t)(kk >> 32));
            g_topidx[r] = 0xFFFFFFFFu - (uint32_t)(kk & 0xFFFFFFFFull);
        } else {
            g_sc[r] = NEGF;
            g_topidx[r] = 0xFFFFFFFFu;
        }
    }
}

// ---------------------------------------------------------------------------
__global__ void k_boxes(const float* __restrict__ bbox,
                        const float* __restrict__ iminfo) {
    int r = blockIdx.x * blockDim.x + threadIdx.x;
    if (r >= PRE_N) return;
    if (r >= g_ntop) {
        g_box[r] = make_float4(0.f, 0.f, 0.f, 0.f);
        return;
    }
    uint32_t idx = g_topidx[r];
    int a = (int)(idx % NA);
    int loc = (int)(idx / NA);
    float h_im = iminfo[0], w_im = iminfo[1];
    g_box[r] = decode_box(loc, a, bbox, h_im, w_im);
}

// ---------------------------------------------------------------------------
// 64x64 IoU tiles, one thread = one row, cols in smem. Upper triangle only.
__global__ void k_mask() {
    int rg = blockIdx.y, cg = blockIdx.x;
    if (cg < rg) return;
    __shared__ float4 cb[64];
    int t = threadIdx.x;
    int c = cg * 64 + t;
    cb[t] = (c < PRE_N) ? g_box[c] : make_float4(0.f, 0.f, 0.f, 0.f);
    __syncthreads();
    int r = rg * 64 + t;
    if (r >= PRE_N) return;
    float4 rb = g_box[r];
    float ra = ((rb.z + 1.0f) - rb.x) * ((rb.w + 1.0f) - rb.y);
    unsigned long long word = 0ull;
#pragma unroll 8
    for (int j = 0; j < 64; j++) {
        int cj = cg * 64 + j;
        if (cj >= PRE_N) break;
        float4 b = cb[j];
        float w = (fminf(rb.z, b.z) + 1.0f) - fmaxf(rb.x, b.x);
        float h = (fminf(rb.w, b.w) + 1.0f) - fmaxf(rb.y, b.y);
        w = fmaxf(w, 0.0f);
        h = fmaxf(h, 0.0f);
        float inter = w * h;
        float ba = ((b.z + 1.0f) - b.x) * ((b.w + 1.0f) - b.y);
        float iou = __fdiv_rn(inter, ra + ba - inter);
        if (iou > 0.7f) word |= (1ull << j);
    }
    g_mask[(size_t)r * NWORDS + cg] = word;
}

// ---------------------------------------------------------------------------
// Group-batched sequential NMS reduce + output assembly. Single block, 1024 thr.
__global__ void k_reduce(float* __restrict__ out) {
    __shared__ unsigned long long remv[NWORDS];
    __shared__ unsigned long long diag[64];
    __shared__ unsigned char keep[PRE_N];
    __shared__ int kept_rows[64];
    __shared__ int s_nk;
    __shared__ int tcnt[1024];

    int t = threadIdx.x;
    int ntop = g_ntop;
    for (int i = t; i < NWORDS; i += blockDim.x) remv[i] = 0ull;
    __syncthreads();

    for (int g = 0; g < NWORDS; g++) {
        if (t < 64) {
            int r = g * 64 + t;
            diag[t] = (r < PRE_N) ? g_mask[(size_t)r * NWORDS + g] : 0ull;
        }
        __syncthreads();
        if (t == 0) {
            unsigned long long word = remv[g];
            int nk = 0;
            for (int b = 0; b < 64; b++) {
                int r = g * 64 + b;
                if (r >= PRE_N) break;
                if (r >= ntop) { keep[r] = 0; continue; }
                if (!((word >> b) & 1ull)) {
                    keep[r] = 1;
                    kept_rows[nk++] = r;
                    word |= diag[b];
                } else {
                    keep[r] = 0;
                }
            }
            s_nk = nk;
        }
        __syncthreads();
        int nk = s_nk;
        int gg = g + 1 + t;
        if (gg < NWORDS) {
            unsigned long long acc = 0ull;
            for (int k = 0; k < nk; k++)
                acc |= g_mask[(size_t)kept_rows[k] * NWORDS + gg];
            remv[gg] |= acc;
        }
        __syncthreads();
    }

    // order-preserving compaction of kept rows -> first POST_N outputs
    const int per = (PRE_N + 1023) / 1024;   // 6
    int base = t * per;
    int c = 0;
    for (int i = 0; i < per; i++) {
        int r = base + i;
        if (r < PRE_N && keep[r]) c++;
    }
    tcnt[t] = c;
    __syncthreads();
    for (int off = 1; off < 1024; off <<= 1) {
        int v = (t >= off) ? tcnt[t - off] : 0;
        __syncthreads();
        tcnt[t] += v;
        __syncthreads();
    }
    int rank = tcnt[t] - c;   // exclusive prefix
    for (int i = 0; i < per; i++) {
        int r = base + i;
        if (r < PRE_N && keep[r]) {
            if (rank < POST_N) {
                float4 bx = g_box[r];
                out[rank * 5 + 0] = 0.0f;
                out[rank * 5 + 1] = bx.x;
                out[rank * 5 + 2] = bx.y;
                out[rank * 5 + 3] = bx.z;
                out[rank * 5 + 4] = bx.w;
                out[POST_N * 5 + rank] = g_sc[r];
            }
            rank++;
        }
    }
    int kept_total = tcnt[1023];
    for (int r2 = t; r2 < POST_N; r2 += blockDim.x) {
        if (r2 >= kept_total) {
            out[r2 * 5 + 0] = 0.0f;
            out[r2 * 5 + 1] = 0.0f;
            out[r2 * 5 + 2] = 0.0f;
            out[r2 * 5 + 3] = 0.0f;
            out[r2 * 5 + 4] = 0.0f;
            out[POST_N * 5 + r2] = 0.0f;
        }
    }
}

// ---------------------------------------------------------------------------
extern "C" void kernel_launch(void* const* d_in, const int* in_sizes, int n_in,
                              void* d_out, int out_size) {
    const float* cls    = (const float*)d_in[0];   // (1, 24, 512, 768)
    const float* bbox   = (const float*)d_in[1];   // (1, 48, 512, 768)
    const float* iminfo = (const float*)d_in[2];   // (1, 3)
    float* out = (float*)d_out;                    // 300*5 rois + 300 scores

    (void)in_sizes; (void)n_in; (void)out_size;

    cudaFuncSetAttribute(k_sort, cudaFuncAttributeMaxDynamicSharedMemorySize,
                         CAND_CAP * (int)sizeof(unsigned long long));

    k_zero<<<NBINS / 4 / 256, 256>>>();
    k_score<<<(HW + 255) / 256, 256>>>(cls, bbox, iminfo);
    k_thresh<<<1, 1024>>>();
    k_compact<<<(NTOT + 255) / 256, 256>>>();
    k_sort<<<1, 1024, CAND_CAP * (int)sizeof(unsigned long long)>>>();
    k_boxes<<<(PRE_N + 255) / 256, 256>>>(bbox, iminfo);
    dim3 mgrid(NWORDS, NWORDS);
    k_mask<<<mgrid, 64>>>();
    k_reduce<<<1, 1024>>>(out);
}

// round 11
// speedup vs baseline: 1.5513x; 1.5513x over previous
#include <cuda_runtime.h>
#include <cstdint>

// ---------------------------------------------------------------------------
// RPN proposal layer for GB300.
//   k_zero    : clear histogram + counters
//   k_score   : decode all 4.7M boxes (vectorized x4), histogram valid scores
//   k_coarse  : 1024-block coalesced coarse reduction of histogram
//   k_thresh  : 1-block parallel suffix scans -> threshold bin for top-6000
//   k_compact : rescan cls (uint4), decode+validate passers, push candidates
//   k_sort    : single-block bitonic sort (exact stable top-k)
//   k_boxes   : recompute/clip boxes for selected 6000
//   k_mask    : 6000x6000 IoU bitmask (upper triangle, 64x64 tiles)
//   k_reduce  : ffs-skip greedy-NMS reduce + popcount output compaction
// ---------------------------------------------------------------------------

#define FH 512
#define FW 768
#define HW (FH * FW)            // 393216
#define NA 12
#define NTOT (HW * NA)          // 4718592
#define NBINS (1 << 20)
#define KSHIFT 12               // histogram on top 20 bits of float
#define CAND_CAP 16384
#define PRE_N 6000
#define POST_N 300
#define NWORDS 94               // ceil(6000/64)
#define NEGF (-1e30f)

typedef unsigned long long u64;

__constant__ float c_aw[NA] = {92.f,184.f,368.f,736.f, 64.f,128.f,256.f,512.f, 44.f, 88.f,176.f,352.f};
__constant__ float c_ah[NA] = {48.f, 96.f,192.f,384.f, 64.f,128.f,256.f,512.f, 88.f,176.f,352.f,704.f};

__device__ __align__(16) uint32_t g_hist[NBINS];
__device__ __align__(16) uint32_t g_csum[1024];
__device__ u64 g_cand[CAND_CAP];
__device__ int g_cand_count;
__device__ uint32_t g_thresh_bin;
__device__ int g_ntop;
__device__ float4 g_box[PRE_N];
__device__ float g_sc[PRE_N];
__device__ uint32_t g_topidx[PRE_N];
__device__ u64 g_mask[PRE_N * NWORDS];

// ---------------------------------------------------------------------------
__global__ void k_zero() {
    int i = blockIdx.x * blockDim.x + threadIdx.x;
    if (i < NBINS / 4) {
        reinterpret_cast<uint4*>(g_hist)[i] = make_uint4(0u, 0u, 0u, 0u);
    }
    if (i == 0) g_cand_count = 0;
}

// ---------------------------------------------------------------------------
__device__ __forceinline__ float4 decode_box(int loc, int a,
                                             const float* __restrict__ bbox,
                                             float h_im, float w_im) {
    int wl = loc % FW, hl = loc / FW;
    float cx = 8.0f + 16.0f * (float)wl;
    float cy = 8.0f + 16.0f * (float)hl;
    const float* bp = bbox + (size_t)(4 * a) * HW + loc;
    float dx = bp[0];
    float dy = bp[HW];
    float dw = bp[2 * HW];
    float dh = bp[3 * HW];
    float wA = c_aw[a], hA = c_ah[a];
    float pcx = dx * wA + cx;
    float pcy = dy * hA + cy;
    float pw = expf(dw) * wA;
    float ph = expf(dh) * hA;
    float4 r;
    r.x = fminf(fmaxf(pcx - 0.5f * pw, 0.0f), w_im - 1.0f);
    r.y = fminf(fmaxf(pcy - 0.5f * ph, 0.0f), h_im - 1.0f);
    r.z = fminf(fmaxf(pcx + 0.5f * pw, 0.0f), w_im - 1.0f);
    r.w = fminf(fmaxf(pcy + 0.5f * ph, 0.0f), h_im - 1.0f);
    return r;
}

// ---------------------------------------------------------------------------
// One thread = 4 consecutive locations (same feature row: FW % 4 == 0).
__global__ void k_score(const float* __restrict__ cls,
                        const float* __restrict__ bbox,
                        const float* __restrict__ iminfo) {
    int q = blockIdx.x * blockDim.x + threadIdx.x;
    if (q >= HW / 4) return;
    int loc0 = q << 2;
    float h_im = iminfo[0], w_im = iminfo[1];
    float ms = 16.0f * iminfo[2] - 1.0f;
    int wl = loc0 % FW, hl = loc0 / FW;
    float cy = 8.0f + 16.0f * (float)hl;
    float cxb = 8.0f + 16.0f * (float)wl;

    for (int a = 0; a < NA; a++) {
        float4 s4 = *reinterpret_cast<const float4*>(cls + (size_t)(NA + a) * HW + loc0);
        const float* bp = bbox + (size_t)(4 * a) * HW + loc0;
        float4 dx4 = *reinterpret_cast<const float4*>(bp);
        float4 dy4 = *reinterpret_cast<const float4*>(bp + HW);
        float4 dw4 = *reinterpret_cast<const float4*>(bp + 2 * HW);
        float4 dh4 = *reinterpret_cast<const float4*>(bp + 3 * HW);
        float wA = c_aw[a], hA = c_ah[a];
        float sc[4] = {s4.x, s4.y, s4.z, s4.w};
        float dx[4] = {dx4.x, dx4.y, dx4.z, dx4.w};
        float dy[4] = {dy4.x, dy4.y, dy4.z, dy4.w};
        float dw[4] = {dw4.x, dw4.y, dw4.z, dw4.w};
        float dh[4] = {dh4.x, dh4.y, dh4.z, dh4.w};
#pragma unroll
        for (int l = 0; l < 4; l++) {
            float cx = cxb + 16.0f * (float)l;
            float pcx = dx[l] * wA + cx;
            float pcy = dy[l] * hA + cy;
            float pw = expf(dw[l]) * wA;
            float ph = expf(dh[l]) * hA;
            float x1 = fminf(fmaxf(pcx - 0.5f * pw, 0.0f), w_im - 1.0f);
            float y1 = fminf(fmaxf(pcy - 0.5f * ph, 0.0f), h_im - 1.0f);
            float x2 = fminf(fmaxf(pcx + 0.5f * pw, 0.0f), w_im - 1.0f);
            float y2 = fminf(fmaxf(pcy + 0.5f * ph, 0.0f), h_im - 1.0f);
            bool valid = (x2 - x1 >= ms) && (y2 - y1 >= ms);
            if (valid) atomicAdd(&g_hist[__float_as_uint(sc[l]) >> KSHIFT], 1u);
        }
    }
}

// ---------------------------------------------------------------------------
// 1024 blocks x 256 threads, fully coalesced: block b sums bins [b*1024, b*1024+1024).
__global__ void k_coarse() {
    __shared__ uint32_t red[8];
    int b = blockIdx.x, t = threadIdx.x;
    uint4 v = reinterpret_cast<const uint4*>(g_hist)[b * 256 + t];
    uint32_t s = v.x + v.y + v.z + v.w;
#pragma unroll
    for (int o = 16; o > 0; o >>= 1) s += __shfl_down_sync(0xFFFFFFFFu, s, o);
    if ((t & 31) == 0) red[t >> 5] = s;
    __syncthreads();
    if (t < 8) {
        uint32_t x = red[t];
#pragma unroll
        for (int o = 4; o > 0; o >>= 1) x += __shfl_down_sync(0xFFu, x, o);
        if (t == 0) g_csum[b] = x;
    }
}

// ---------------------------------------------------------------------------
__device__ __forceinline__ uint32_t warp_iscan(uint32_t v, int lane) {
#pragma unroll
    for (int o = 1; o < 32; o <<= 1) {
        uint32_t n = __shfl_up_sync(0xFFFFFFFFu, v, o);
        if (lane >= o) v += n;
    }
    return v;
}

// Single block, 1024 threads: two parallel suffix scans find the bin T such
// that count(bin >= T) >= PRE_N.
__global__ void __launch_bounds__(1024, 1) k_thresh() {
    __shared__ uint32_t wsum[32];
    __shared__ int s_tc;
    __shared__ uint32_t s_above;
    int t = threadIdx.x, lane = t & 31, wid = t >> 5;
    if (t == 0) s_tc = -1;
    __syncthreads();

    // stage 1: coarse chunks, scanned from the top (reverse index)
    uint32_t v = g_csum[1023 - t];
    uint32_t p = warp_iscan(v, lane);
    if (lane == 31) wsum[wid] = p;
    __syncthreads();
    if (wid == 0) { uint32_t w = wsum[lane]; w = warp_iscan(w, lane); wsum[lane] = w; }
    __syncthreads();
    uint32_t incl = p + (wid ? wsum[wid - 1] : 0u);
    uint32_t excl = incl - v;
    if (incl >= PRE_N && excl < PRE_N) { s_tc = 1023 - t; s_above = excl; }
    __syncthreads();
    int tc = s_tc;
    if (tc < 0) { if (t == 0) g_thresh_bin = 1; return; }
    uint32_t above = s_above;
    __syncthreads();

    // stage 2: fine bins within chunk tc
    uint32_t v2 = g_hist[tc * 1024 + (1023 - t)];
    uint32_t p2 = warp_iscan(v2, lane);
    if (lane == 31) wsum[wid] = p2;
    __syncthreads();
    if (wid == 0) { uint32_t w = wsum[lane]; w = warp_iscan(w, lane); wsum[lane] = w; }
    __syncthreads();
    uint32_t incl2 = above + p2 + (wid ? wsum[wid - 1] : 0u);
    uint32_t excl2 = incl2 - v2;
    if (incl2 >= PRE_N && excl2 < PRE_N) {
        uint32_t T = (uint32_t)(tc * 1024 + (1023 - t));
        if (T < 1) T = 1;
        g_thresh_bin = T;
    }
}

// ---------------------------------------------------------------------------
// Rescan cls scores (uint4); decode+validate only threshold-bin passers.
__global__ void k_compact(const float* __restrict__ cls,
                          const float* __restrict__ bbox,
                          const float* __restrict__ iminfo) {
    int q = blockIdx.x * blockDim.x + threadIdx.x;
    if (q >= NTOT / 4) return;
    uint4 v = reinterpret_cast<const uint4*>(cls)[(size_t)(NA * HW / 4) + q];
    uint32_t T = g_thresh_bin;
    uint32_t ks[4] = {v.x, v.y, v.z, v.w};
#pragma unroll
    for (int l = 0; l < 4; l++) {
        uint32_t key = ks[l];
        if ((key >> KSHIFT) >= T) {
            int p = q * 4 + l;
            int a = p / HW;
            int loc = p - a * HW;
            float h_im = iminfo[0], w_im = iminfo[1];
            float ms = 16.0f * iminfo[2] - 1.0f;
            float4 b = decode_box(loc, a, bbox, h_im, w_im);
            if ((b.z - b.x >= ms) && (b.w - b.y >= ms)) {
                uint32_t idx = (uint32_t)(loc * NA + a);  // original flat order
                int pos = atomicAdd(&g_cand_count, 1);
                if (pos < CAND_CAP)
                    g_cand[pos] = ((u64)key << 32) | (0xFFFFFFFFu - idx);
            }
        }
    }
}

// ---------------------------------------------------------------------------
// Single-block bitonic sort (descending). Key = (score_bits<<32) | ~idx.
extern __shared__ u64 s_keys[];
__global__ void __launch_bounds__(1024, 1) k_sort() {
    int n = g_cand_count;
    if (n > CAND_CAP) n = CAND_CAP;
    int np = 2;
    while (np < n) np <<= 1;
    int t = threadIdx.x;
    for (int i = t; i < np; i += blockDim.x)
        s_keys[i] = (i < n) ? g_cand[i] : 0ull;
    __syncthreads();
    for (int k = 2; k <= np; k <<= 1) {
        for (int j = k >> 1; j > 0; j >>= 1) {
            for (int i = t; i < np; i += blockDim.x) {
                int l = i ^ j;
                if (l > i) {
                    bool desc = ((i & k) == 0);
                    u64 a = s_keys[i];
                    u64 b = s_keys[l];
                    if ((a < b) == desc) { s_keys[i] = b; s_keys[l] = a; }
                }
            }
            __syncthreads();
        }
    }
    int ntop = (n < PRE_N) ? n : PRE_N;
    if (t == 0) g_ntop = ntop;
    for (int r = t; r < PRE_N; r += blockDim.x) {
        if (r < ntop) {
            u64 kk = s_keys[r];
            g_sc[r] = __uint_as_float((uint32_t)(kk >> 32));
            g_topidx[r] = 0xFFFFFFFFu - (uint32_t)(kk & 0xFFFFFFFFull);
        } else {
            g_sc[r] = NEGF;
            g_topidx[r] = 0xFFFFFFFFu;
        }
    }
}

// ---------------------------------------------------------------------------
__global__ void k_boxes(const float* __restrict__ bbox,
                        const float* __restrict__ iminfo) {
    int r = blockIdx.x * blockDim.x + threadIdx.x;
    if (r >= PRE_N) return;
    if (r >= g_ntop) { g_box[r] = make_float4(0.f, 0.f, 0.f, 0.f); return; }
    uint32_t idx = g_topidx[r];
    int a = (int)(idx % NA);
    int loc = (int)(idx / NA);
    g_box[r] = decode_box(loc, a, bbox, iminfo[0], iminfo[1]);
}

// ---------------------------------------------------------------------------
__global__ void k_mask() {
    int rg = blockIdx.y, cg = blockIdx.x;
    if (cg < rg) return;
    __shared__ float4 cb[64];
    int t = threadIdx.x;
    int c = cg * 64 + t;
    cb[t] = (c < PRE_N) ? g_box[c] : make_float4(0.f, 0.f, 0.f, 0.f);
    __syncthreads();
    int r = rg * 64 + t;
    if (r >= PRE_N) return;
    float4 rb = g_box[r];
    float ra = ((rb.z + 1.0f) - rb.x) * ((rb.w + 1.0f) - rb.y);
    u64 word = 0ull;
#pragma unroll 8
    for (int j = 0; j < 64; j++) {
        int cj = cg * 64 + j;
        if (cj >= PRE_N) break;
        float4 b = cb[j];
        float w = (fminf(rb.z, b.z) + 1.0f) - fmaxf(rb.x, b.x);
        float h = (fminf(rb.w, b.w) + 1.0f) - fmaxf(rb.y, b.y);
        w = fmaxf(w, 0.0f);
        h = fmaxf(h, 0.0f);
        float inter = w * h;
        float ba = ((b.z + 1.0f) - b.x) * ((b.w + 1.0f) - b.y);
        float iou = __fdiv_rn(inter, ra + ba - inter);
        if (iou > 0.7f) word |= (1ull << j);
    }
    g_mask[(size_t)r * NWORDS + cg] = word;
}

// ---------------------------------------------------------------------------
// Greedy-NMS reduce: ffs-skip serial phase per 64-row group + parallel
// column OR, then popcount-based output compaction. Single block, 1024 thr.
__global__ void __launch_bounds__(1024, 1) k_reduce(float* __restrict__ out) {
    __shared__ u64 remv[NWORDS];
    __shared__ u64 diag[64];
    __shared__ u64 keepw[NWORDS];
    __shared__ int kept_rows[64];
    __shared__ int s_nk;
    __shared__ int sbase[NWORDS];
    __shared__ int s_total;

    int t = threadIdx.x;
    int ntop = g_ntop;
    for (int i = t; i < NWORDS; i += blockDim.x) { remv[i] = 0ull; keepw[i] = 0ull; }
    __syncthreads();

    for (int g = 0; g < NWORDS; g++) {
        if (t < 64) {
            int r = g * 64 + t;
            diag[t] = (r < PRE_N) ? g_mask[(size_t)r * NWORDS + g] : ~0ull;
        }
        __syncthreads();
        if (t == 0) {
            int base = g * 64;
            int lim = ntop - base;
            if (lim > 64) lim = 64;
            u64 mask = (lim >= 64) ? ~0ull : ((lim <= 0) ? 0ull : ((1ull << lim) - 1ull));
            u64 alive = ~remv[g] & mask;
            u64 kw = 0ull;
            int nk = 0;
            while (alive) {
                int b = __ffsll(alive) - 1;
                kw |= (1ull << b);
                kept_rows[nk++] = base + b;
                alive &= ~diag[b];
            }
            keepw[g] = kw;
            s_nk = nk;
        }
        __syncthreads();
        int nk = s_nk;
        int gg = g + 1 + t;
        if (gg < NWORDS) {
            u64 acc = 0ull;
            for (int k = 0; k < nk; k++)
                acc |= g_mask[(size_t)kept_rows[k] * NWORDS + gg];
            remv[gg] |= acc;
        }
        __syncthreads();
    }

    // popcount compaction: exact score-descending order is preserved because
    // groups are scanned in index order and bits within a group ascend.
    if (t == 0) {
        int acc = 0;
        for (int g = 0; g < NWORDS; g++) { sbase[g] = acc; acc += __popcll(keepw[g]); }
        s_total = acc;
    }
    __syncthreads();
    if (t < NWORDS) {
        u64 kw = keepw[t];
        int rank = sbase[t];
        while (kw && rank < POST_N) {
            int b = __ffsll(kw) - 1;
            kw &= kw - 1;
            int r = t * 64 + b;
            float4 bx = g_box[r];
            out[rank * 5 + 0] = 0.0f;
            out[rank * 5 + 1] = bx.x;
            out[rank * 5 + 2] = bx.y;
            out[rank * 5 + 3] = bx.z;
            out[rank * 5 + 4] = bx.w;
            out[POST_N * 5 + rank] = g_sc[r];
            rank++;
        }
    }
    __syncthreads();
    int kept_total = s_total;
    for (int r2 = t; r2 < POST_N; r2 += blockDim.x) {
        if (r2 >= kept_total) {
            out[r2 * 5 + 0] = 0.0f;
            out[r2 * 5 + 1] = 0.0f;
            out[r2 * 5 + 2] = 0.0f;
            out[r2 * 5 + 3] = 0.0f;
            out[r2 * 5 + 4] = 0.0f;
            out[POST_N * 5 + r2] = 0.0f;
        }
    }
}

// ---------------------------------------------------------------------------
extern "C" void kernel_launch(void* const* d_in, const int* in_sizes, int n_in,
                              void* d_out, int out_size) {
    const float* cls    = (const float*)d_in[0];   // (1, 24, 512, 768)
    const float* bbox   = (const float*)d_in[1];   // (1, 48, 512, 768)
    const float* iminfo = (const float*)d_in[2];   // (1, 3)
    float* out = (float*)d_out;                    // 300*5 rois + 300 scores
    (void)in_sizes; (void)n_in; (void)out_size;

    cudaFuncSetAttribute(k_sort, cudaFuncAttributeMaxDynamicSharedMemorySize,
                         CAND_CAP * (int)sizeof(u64));

    k_zero<<<NBINS / 4 / 256, 256>>>();
    k_score<<<(HW / 4 + 255) / 256, 256>>>(cls, bbox, iminfo);
    k_coarse<<<1024, 256>>>();
    k_thresh<<<1, 1024>>>();
    k_compact<<<(NTOT / 4 + 255) / 256, 256>>>(cls, bbox, iminfo);
    k_sort<<<1, 1024, CAND_CAP * (int)sizeof(u64)>>>();
    k_boxes<<<(PRE_N + 255) / 256, 256>>>(bbox, iminfo);
    dim3 mgrid(NWORDS, NWORDS);
    k_mask<<<mgrid, 64>>>();
    k_reduce<<<1, 1024>>>(out);
}